// round 12
// baseline (speedup 1.0000x reference)
#include <cuda_runtime.h>
#include <cuda_bf16.h>
#include <cuda_fp16.h>

// Problem constants (fixed by the reference)
#define NSPEC      16
#define DIMRAD     16
#define DIMRADANG  8
#define NF         5          // NMAX_ANGLE + 1
#define VDIM       2
#define ROW        432        // 16 + 256 + 160
#define RAD_OFF    16
#define ANG_OFF    272
#define MAX_EDGES      1000000
#define MAX_EDGES_ANG  500000
#define MAX_ANGLES     2000000
#define MAX_ATOMS      50000
#define NB_MAX         64

#define ETA_R  10.24f                 // (16/5)^2
#define STEP_R 0.33333333333333333f   // 5/15
#define ETA2   5.2244897959183673f    // (8/3.5)^2
#define KA    (-7.5373556525f)        // -ETA2  * log2(e)
#define KR    (-14.7731972231f)       // -ETA_R * log2(e)

// scratch (static __device__ — zero-initialized at module load, no runtime alloc)
__device__ float4 g_eang[MAX_EDGES_ANG];     // {d, sw, v0, v1} per angular edge
__device__ int    g_cnt[2][MAX_ATOMS];       // zero at kernel_launch entry (invariant)
__device__ int    g_off[2][MAX_ATOMS + 1];
__device__ int    g_cur[2][MAX_ATOMS];
__device__ unsigned g_look[2][NB_MAX];       // lookback channels; zero at entry (invariant)
__device__ int    g_done;                    // self-resetting
__device__ float4 g_arec[MAX_ANGLES];        // {d12, ca, half2(v0,v1), half2(v2,v3)}
__device__ float2 g_rrec[MAX_EDGES];         // {d, sw with species in low 4 mantissa bits}

__device__ __forceinline__ float ex2f(float x) {
    float y;
    asm("ex2.approx.ftz.f32 %0, %1;" : "=f"(y) : "f"(x));
    return y;
}

// ---------------------------------------------------------------------------
// K1: packed angular-edge table + both histograms (one-hot lives in accum).
// ---------------------------------------------------------------------------
__global__ void prep_hist_kernel(const int* __restrict__ species,
                                 const int* __restrict__ edge_dst_ang,
                                 const float* __restrict__ vtab,
                                 const float* __restrict__ dang,
                                 const float* __restrict__ swang,
                                 const int* __restrict__ central,
                                 const int* __restrict__ esrc,
                                 int n_edges_ang, int n_angles, int n_edges) {
    int i = blockIdx.x * blockDim.x + threadIdx.x;
    if (i < n_edges_ang) {
        int s = species[edge_dst_ang[i]];
        g_eang[i] = make_float4(dang[i], swang[i],
                                vtab[s * VDIM + 0], vtab[s * VDIM + 1]);
    }
    if (i < n_angles) atomicAdd(&g_cnt[0][central[i]], 1);
    if (i < n_edges)  atomicAdd(&g_cnt[1][esrc[i]], 1);
}

// ---------------------------------------------------------------------------
// K2: single-pass scan (decoupled lookback), both arrays packed in u64.
// ---------------------------------------------------------------------------
__global__ void scan_kernel(int n, int nb) {
    __shared__ unsigned long long ws[32];
    __shared__ unsigned long long s_base;
    int b = blockIdx.x, tid = threadIdx.x, lane = tid & 31, w = tid >> 5;
    int i = b * 1024 + tid;
    unsigned c0 = (i < n) ? (unsigned)g_cnt[0][i] : 0u;
    unsigned c1 = (i < n) ? (unsigned)g_cnt[1][i] : 0u;
    unsigned long long v = (unsigned long long)c0 | ((unsigned long long)c1 << 32);
    unsigned long long x = v;
    #pragma unroll
    for (int d = 1; d < 32; d <<= 1) {
        unsigned long long t = __shfl_up_sync(0xffffffffu, x, d);
        if (lane >= d) x += t;
    }
    if (lane == 31) ws[w] = x;
    __syncthreads();
    if (w == 0) {
        unsigned long long s = ws[lane];
        #pragma unroll
        for (int d = 1; d < 32; d <<= 1) {
            unsigned long long t = __shfl_up_sync(0xffffffffu, s, d);
            if (lane >= d) s += t;
        }
        ws[lane] = s;
    }
    __syncthreads();
    unsigned long long incl  = x + (w ? ws[w - 1] : 0);
    unsigned long long total = ws[31];

    if (tid == 0) {
        unsigned t0 = (unsigned)(total & 0xffffffffull);
        unsigned t1 = (unsigned)(total >> 32);
        unsigned run0 = 0, run1 = 0;
        if (b == 0) {
            ((volatile unsigned*)g_look[0])[0] = (2u << 30) | t0;
            ((volatile unsigned*)g_look[1])[0] = (2u << 30) | t1;
        } else {
            ((volatile unsigned*)g_look[0])[b] = (1u << 30) | t0;
            ((volatile unsigned*)g_look[1])[b] = (1u << 30) | t1;
            #pragma unroll 1
            for (int ch = 0; ch < 2; ch++) {
                unsigned run = 0;
                int j = b - 1;
                while (true) {
                    unsigned s = ((volatile unsigned*)g_look[ch])[j];
                    unsigned f = s >> 30;
                    if (f == 0u) continue;
                    run += s & 0x3fffffffu;
                    if (f == 2u) break;
                    j--;
                }
                if (ch == 0) run0 = run; else run1 = run;
            }
            ((volatile unsigned*)g_look[0])[b] = (2u << 30) | (run0 + t0);
            ((volatile unsigned*)g_look[1])[b] = (2u << 30) | (run1 + t1);
        }
        s_base = (unsigned long long)run0 | ((unsigned long long)run1 << 32);
    }
    __syncthreads();
    unsigned long long base = s_base;
    if (i < n) {
        int off0 = (int)((unsigned)(base & 0xffffffffull) + (unsigned)(incl & 0xffffffffull) - c0);
        int off1 = (int)((unsigned)(base >> 32) + (unsigned)(incl >> 32) - c1);
        g_off[0][i] = off0; g_cur[0][i] = off0; g_cnt[0][i] = 0;
        g_off[1][i] = off1; g_cur[1][i] = off1; g_cnt[1][i] = 0;
        if (i == n - 1) {
            g_off[0][n] = off0 + (int)c0;
            g_off[1][n] = off1 + (int)c1;
        }
    }
    if (tid == 0) {
        __threadfence();
        int d = atomicAdd(&g_done, 1);
        if (d == nb - 1) {
            for (int j = 0; j < nb; j++) { g_look[0][j] = 0u; g_look[1][j] = 0u; }
            g_done = 0;
        }
    }
}

// ---------------------------------------------------------------------------
// K3: build records for both CSRs (atom-sorted slots).
// ---------------------------------------------------------------------------
__global__ void scatter_kernel(const float* __restrict__ angles,
                               const int*  __restrict__ central,
                               const int*  __restrict__ asrc,
                               const int*  __restrict__ adst,
                               const float* __restrict__ dist,
                               const float* __restrict__ sw,
                               const int*  __restrict__ esrc,
                               const int*  __restrict__ edst,
                               const int*  __restrict__ species,
                               int n_angles, int n_edges) {
    int t = blockIdx.x * blockDim.x + threadIdx.x;
    if (t < n_angles) {
        int es = asrc[t], ed = adst[t];
        float4 ps = g_eang[es];
        float4 pd = g_eang[ed];
        float d12  = 0.5f * (ps.x + pd.x);
        float sw12 = ps.y * pd.y;
        float ca   = __cosf(angles[t]);
        float vp0 = ps.z + pd.z, vp1 = ps.w + pd.w;
        float vm0 = ps.z * pd.z, vm1 = ps.w * pd.w;
        __half2 h01 = __floats2half2_rn(sw12 * vp0 * vm0, sw12 * vp0 * vm1);
        __half2 h23 = __floats2half2_rn(sw12 * vp1 * vm0, sw12 * vp1 * vm1);
        int pos = atomicAdd(&g_cur[0][central[t]], 1);
        float4 r;
        r.x = d12;
        r.y = ca;
        r.z = __uint_as_float(*reinterpret_cast<unsigned*>(&h01));
        r.w = __uint_as_float(*reinterpret_cast<unsigned*>(&h23));
        g_arec[pos] = r;
    }
    if (t < n_edges) {
        float d = dist[t], s = sw[t];
        int sd = species[edst[t]];
        int pos = atomicAdd(&g_cur[1][esrc[t]], 1);
        unsigned sb = (__float_as_uint(s) & ~15u) | (unsigned)sd;
        g_rrec[pos] = make_float2(d, __uint_as_float(sb));
    }
}

// ---------------------------------------------------------------------------
// K4: fused accumulation. One warp per atom; no atomics.
// Angular: lane = (ra = lane>>2, slot = lane&3); slot indexes one of 4
// records per iteration; lane keeps all 4 v-moments (20 regs). Partials
// combined through a conflict-free smem transpose (stride 21).
// ---------------------------------------------------------------------------
__global__ void __launch_bounds__(256) accum_kernel(float* __restrict__ out,
                             const int* __restrict__ species, int n_atoms) {
    // per-warp buffer: radial uses [0..544), angular partials use [0..672)
    __shared__ float sbuf[8][672];
    int w    = threadIdx.x >> 5;
    int lane = threadIdx.x & 31;
    int atom = blockIdx.x * 8 + w;
    if (atom >= n_atoms) return;

    // ---- one-hot
    if (lane < NSPEC) {
        int sp = species[atom];
        out[(long)atom * ROW + lane] = (lane == sp) ? 1.0f : 0.0f;
    }

    // ---- radial (half-warp per species-bin buffer, 16 lanes = 16 centers)
    float* mybuf = &sbuf[w][0];
    for (int k = lane; k < 2 * 16 * 17; k += 32) mybuf[k] = 0.f;
    __syncwarp();

    int hw = lane >> 4, lr = lane & 15;
    float ctr = STEP_R * (float)lr;
    float BR1 = -2.0f * KR * ctr;
    float BR2 = KR * ctr * ctr;
    float* hbuf = &sbuf[w][hw * 272] + lr * 17;
    {
        int s0 = g_off[1][atom], e0 = g_off[1][atom + 1];
        for (int i = s0 + hw; i < e0; i += 2) {
            float2 r = g_rrec[i];
            int sd = (int)(__float_as_uint(r.y) & 15u);
            float q = fmaf(KR, r.x, BR1);
            float v = r.y * ex2f(fmaf(q, r.x, BR2));
            hbuf[sd] += v;
        }
    }
    __syncwarp();
    {
        float* obase = out + (long)atom * ROW + RAD_OFF;
        #pragma unroll
        for (int k = 0; k < 8; k++) {
            int idx = k * 32 + lane;          // coalesced
            int r = idx >> 4, s = idx & 15;
            obase[idx] = sbuf[w][r * 17 + s] + sbuf[w][272 + r * 17 + s];
        }
    }
    __syncwarp();   // radial reads done before buffer reuse

    // ---- angular: lane = (ra, slot); 4 records per warp iteration
    int ra = lane >> 2, slot = lane & 3;
    float center = 0.5f * (float)ra;
    float B1 = -2.0f * KA * center;       // q = fma(KA, x, B1)
    float B2 = KA * center * center;      // e = fma(q, x, B2)

    float m0x = 0.f, m0y = 0.f, m0z = 0.f, m0w = 0.f;
    float m1x = 0.f, m1y = 0.f, m1z = 0.f, m1w = 0.f;
    float m2x = 0.f, m2y = 0.f, m2z = 0.f, m2w = 0.f;
    float m3x = 0.f, m3y = 0.f, m3z = 0.f, m3w = 0.f;
    float m4x = 0.f, m4y = 0.f, m4z = 0.f, m4w = 0.f;

    int s1 = g_off[0][atom];
    int n  = g_off[0][atom + 1] - s1;
    const float4* __restrict__ rp = g_arec + s1;

    int base = 0;
    for (; base + 4 <= n; base += 4) {
        float4 c = rp[base + slot];
        unsigned uz = __float_as_uint(c.z);
        unsigned uw = __float_as_uint(c.w);
        float2 f01 = __half22float2(*reinterpret_cast<__half2*>(&uz));
        float2 f23 = __half22float2(*reinterpret_cast<__half2*>(&uw));
        float qq = fmaf(KA, c.x, B1);
        float e  = ex2f(fmaf(qq, c.x, B2));
        float ca = c.y;
        float ca2 = ca * ca;
        float e1m = ca * e;
        float e2m = ca2 * e;
        float e3m = ca2 * e1m;
        float e4m = ca2 * e2m;
        m0x = fmaf(e,   f01.x, m0x); m0y = fmaf(e,   f01.y, m0y);
        m0z = fmaf(e,   f23.x, m0z); m0w = fmaf(e,   f23.y, m0w);
        m1x = fmaf(e1m, f01.x, m1x); m1y = fmaf(e1m, f01.y, m1y);
        m1z = fmaf(e1m, f23.x, m1z); m1w = fmaf(e1m, f23.y, m1w);
        m2x = fmaf(e2m, f01.x, m2x); m2y = fmaf(e2m, f01.y, m2y);
        m2z = fmaf(e2m, f23.x, m2z); m2w = fmaf(e2m, f23.y, m2w);
        m3x = fmaf(e3m, f01.x, m3x); m3y = fmaf(e3m, f01.y, m3y);
        m3z = fmaf(e3m, f23.x, m3z); m3w = fmaf(e3m, f23.y, m3w);
        m4x = fmaf(e4m, f01.x, m4x); m4y = fmaf(e4m, f01.y, m4y);
        m4z = fmaf(e4m, f23.x, m4z); m4w = fmaf(e4m, f23.y, m4w);
    }
    int rem = n - base;
    if (rem > 0) {
        int idx = base + (slot < rem ? slot : rem - 1);
        float4 c = rp[idx];
        unsigned uz = __float_as_uint(c.z);
        unsigned uw = __float_as_uint(c.w);
        float2 f01 = __half22float2(*reinterpret_cast<__half2*>(&uz));
        float2 f23 = __half22float2(*reinterpret_cast<__half2*>(&uw));
        if (slot >= rem) { f01.x = f01.y = f23.x = f23.y = 0.f; }
        float qq = fmaf(KA, c.x, B1);
        float e  = ex2f(fmaf(qq, c.x, B2));
        float ca = c.y;
        float ca2 = ca * ca;
        float e1m = ca * e;
        float e2m = ca2 * e;
        float e3m = ca2 * e1m;
        float e4m = ca2 * e2m;
        m0x = fmaf(e,   f01.x, m0x); m0y = fmaf(e,   f01.y, m0y);
        m0z = fmaf(e,   f23.x, m0z); m0w = fmaf(e,   f23.y, m0w);
        m1x = fmaf(e1m, f01.x, m1x); m1y = fmaf(e1m, f01.y, m1y);
        m1z = fmaf(e1m, f23.x, m1z); m1w = fmaf(e1m, f23.y, m1w);
        m2x = fmaf(e2m, f01.x, m2x); m2y = fmaf(e2m, f01.y, m2y);
        m2z = fmaf(e2m, f23.x, m2z); m2w = fmaf(e2m, f23.y, m2w);
        m3x = fmaf(e3m, f01.x, m3x); m3y = fmaf(e3m, f01.y, m3y);
        m3z = fmaf(e3m, f23.x, m3z); m3w = fmaf(e3m, f23.y, m3w);
        m4x = fmaf(e4m, f01.x, m4x); m4y = fmaf(e4m, f01.y, m4y);
        m4z = fmaf(e4m, f23.x, m4z); m4w = fmaf(e4m, f23.y, m4w);
    }

    // ---- partial reduce through smem: store lane partials (stride 21)
    {
        float* pb = &sbuf[w][lane * 21];
        pb[0]  = m0x; pb[1]  = m0y; pb[2]  = m0z; pb[3]  = m0w;
        pb[4]  = m1x; pb[5]  = m1y; pb[6]  = m1z; pb[7]  = m1w;
        pb[8]  = m2x; pb[9]  = m2y; pb[10] = m2z; pb[11] = m2w;
        pb[12] = m3x; pb[13] = m3y; pb[14] = m3z; pb[15] = m3w;
        pb[16] = m4x; pb[17] = m4y; pb[18] = m4z; pb[19] = m4w;
    }
    __syncwarp();
    // lane (ra, slot) gathers v=slot across the 4 slot-lanes of its ra group
    {
        float M[5];
        #pragma unroll
        for (int f = 0; f < 5; f++) {
            int col = f * 4 + slot;
            M[f] = sbuf[w][(ra * 4 + 0) * 21 + col]
                 + sbuf[w][(ra * 4 + 1) * 21 + col]
                 + sbuf[w][(ra * 4 + 2) * 21 + col]
                 + sbuf[w][(ra * 4 + 3) * 21 + col];
        }
        float* ob = out + (long)atom * ROW + ANG_OFF + ra * 20 + slot;
        ob[0]  = M[0];
        ob[4]  = M[1];
        ob[8]  = 2.0f * M[2] - M[0];
        ob[12] = 4.0f * M[3] - 3.0f * M[1];
        ob[16] = 8.0f * (M[4] - M[2]) + M[0];
    }
}

// ---------------------------------------------------------------------------
// Launch
// ---------------------------------------------------------------------------
extern "C" void kernel_launch(void* const* d_in, const int* in_sizes, int n_in,
                              void* d_out, int out_size) {
    const int*   species      = (const int*)  d_in[0];
    const float* distances    = (const float*)d_in[1];
    const float* switch_      = (const float*)d_in[2];
    const int*   edge_src     = (const int*)  d_in[3];
    const int*   edge_dst     = (const int*)  d_in[4];
    const float* angles       = (const float*)d_in[5];
    const float* dang         = (const float*)d_in[6];
    const float* switch_ang   = (const float*)d_in[7];
    const int*   central_atom = (const int*)  d_in[8];
    const int*   angle_src    = (const int*)  d_in[9];
    const int*   angle_dst    = (const int*)  d_in[10];
    const int*   edge_dst_ang = (const int*)  d_in[11];
    const float* valence_tab  = (const float*)d_in[12];

    float* out = (float*)d_out;

    int n_atoms     = in_sizes[0];
    int n_edges     = in_sizes[1];
    int n_angles    = in_sizes[5];
    int n_edges_ang = in_sizes[6];

    // K1: edge table + histograms (counters zero on entry by invariant)
    int n1 = n_angles > n_edges ? n_angles : n_edges;
    prep_hist_kernel<<<(n1 + 255) / 256, 256>>>(species, edge_dst_ang,
                                                valence_tab, dang, switch_ang,
                                                central_atom, edge_src,
                                                n_edges_ang, n_angles, n_edges);

    // K2: single-pass decoupled-lookback scan (re-zeroes g_cnt / g_look)
    int nb = (n_atoms + 1023) / 1024;
    scan_kernel<<<nb, 1024>>>(n_atoms, nb);

    // K3: scatter records
    scatter_kernel<<<(n1 + 255) / 256, 256>>>(angles, central_atom,
                                              angle_src, angle_dst,
                                              distances, switch_, edge_src,
                                              edge_dst, species,
                                              n_angles, n_edges);

    // K4: fused accumulation (one warp per atom) + one-hot
    accum_kernel<<<(n_atoms + 7) / 8, 256>>>(out, species, n_atoms);
}

// round 13
// speedup vs baseline: 1.0175x; 1.0175x over previous
#include <cuda_runtime.h>
#include <cuda_bf16.h>
#include <cuda_fp16.h>

// Problem constants (fixed by the reference)
#define NSPEC      16
#define DIMRAD     16
#define DIMRADANG  8
#define NF         5          // NMAX_ANGLE + 1
#define VDIM       2
#define ROW        432        // 16 + 256 + 160
#define RAD_OFF    16
#define ANG_OFF    272
#define MAX_EDGES      1000000
#define MAX_EDGES_ANG  500000
#define MAX_ANGLES     2000000
#define MAX_ATOMS      50000
#define NB_MAX         64

#define ETA_R  10.24f                 // (16/5)^2
#define STEP_R 0.33333333333333333f   // 5/15
#define ETA2   5.2244897959183673f    // (8/3.5)^2
#define KA    (-7.5373556525f)        // -ETA2  * log2(e)
#define KR    (-14.7731972231f)       // -ETA_R * log2(e)

// scratch (static __device__ — zero-initialized at module load, no runtime alloc)
__device__ float4 g_eang[MAX_EDGES_ANG];     // {d, sw, v0, v1} per angular edge
__device__ int    g_cnt[2][MAX_ATOMS];       // zero at kernel_launch entry (invariant)
__device__ int    g_off[2][MAX_ATOMS + 1];
__device__ int    g_cur[2][MAX_ATOMS];
__device__ unsigned g_look[2][NB_MAX];       // lookback channels; zero at entry (invariant)
__device__ int    g_done;                    // self-resetting
__device__ float4 g_arec[MAX_ANGLES];        // {d12, ca, half2(v0,v1), half2(v2,v3)}
__device__ float2 g_rrec[MAX_EDGES];         // {d, sw with species in low 4 mantissa bits}

__device__ __forceinline__ float ex2f(float x) {
    float y;
    asm("ex2.approx.ftz.f32 %0, %1;" : "=f"(y) : "f"(x));
    return y;
}

// ---------------------------------------------------------------------------
// K1: both histograms only (eang table build lives in scan; one-hot in accum).
// ---------------------------------------------------------------------------
__global__ void prep_hist_kernel(const int* __restrict__ central,
                                 const int* __restrict__ esrc,
                                 int n_angles, int n_edges) {
    int i = blockIdx.x * blockDim.x + threadIdx.x;
    if (i < n_angles) atomicAdd(&g_cnt[0][central[i]], 1);
    if (i < n_edges)  atomicAdd(&g_cnt[1][esrc[i]], 1);
}

// ---------------------------------------------------------------------------
// K2: single-pass scan (decoupled lookback), both arrays packed in u64.
// Channel word: bits[31:30] flag (0=invalid,1=aggregate,2=prefix), [29:0] value.
// All blocks (<=49) resident in one wave -> spin cannot deadlock.
// Tail: grid-stride build of the packed angular-edge table (chip otherwise idle).
// Resets g_cnt / g_look / g_done for the next call (zero invariant).
// ---------------------------------------------------------------------------
__global__ void scan_kernel(const int* __restrict__ species,
                            const int* __restrict__ edge_dst_ang,
                            const float* __restrict__ vtab,
                            const float* __restrict__ dang,
                            const float* __restrict__ swang,
                            int n_edges_ang, int n, int nb) {
    __shared__ unsigned long long ws[32];
    __shared__ unsigned long long s_base;
    int b = blockIdx.x, tid = threadIdx.x, lane = tid & 31, w = tid >> 5;
    int i = b * 1024 + tid;
    unsigned c0 = (i < n) ? (unsigned)g_cnt[0][i] : 0u;
    unsigned c1 = (i < n) ? (unsigned)g_cnt[1][i] : 0u;
    unsigned long long v = (unsigned long long)c0 | ((unsigned long long)c1 << 32);
    unsigned long long x = v;
    #pragma unroll
    for (int d = 1; d < 32; d <<= 1) {
        unsigned long long t = __shfl_up_sync(0xffffffffu, x, d);
        if (lane >= d) x += t;
    }
    if (lane == 31) ws[w] = x;
    __syncthreads();
    if (w == 0) {
        unsigned long long s = ws[lane];
        #pragma unroll
        for (int d = 1; d < 32; d <<= 1) {
            unsigned long long t = __shfl_up_sync(0xffffffffu, s, d);
            if (lane >= d) s += t;
        }
        ws[lane] = s;
    }
    __syncthreads();
    unsigned long long incl  = x + (w ? ws[w - 1] : 0);
    unsigned long long total = ws[31];

    if (tid == 0) {
        unsigned t0 = (unsigned)(total & 0xffffffffull);
        unsigned t1 = (unsigned)(total >> 32);
        unsigned run0 = 0, run1 = 0;
        if (b == 0) {
            ((volatile unsigned*)g_look[0])[0] = (2u << 30) | t0;
            ((volatile unsigned*)g_look[1])[0] = (2u << 30) | t1;
        } else {
            ((volatile unsigned*)g_look[0])[b] = (1u << 30) | t0;
            ((volatile unsigned*)g_look[1])[b] = (1u << 30) | t1;
            #pragma unroll 1
            for (int ch = 0; ch < 2; ch++) {
                unsigned run = 0;
                int j = b - 1;
                while (true) {
                    unsigned s = ((volatile unsigned*)g_look[ch])[j];
                    unsigned f = s >> 30;
                    if (f == 0u) continue;
                    run += s & 0x3fffffffu;
                    if (f == 2u) break;
                    j--;
                }
                if (ch == 0) run0 = run; else run1 = run;
            }
            ((volatile unsigned*)g_look[0])[b] = (2u << 30) | (run0 + t0);
            ((volatile unsigned*)g_look[1])[b] = (2u << 30) | (run1 + t1);
        }
        s_base = (unsigned long long)run0 | ((unsigned long long)run1 << 32);
    }
    __syncthreads();
    unsigned long long base = s_base;
    if (i < n) {
        int off0 = (int)((unsigned)(base & 0xffffffffull) + (unsigned)(incl & 0xffffffffull) - c0);
        int off1 = (int)((unsigned)(base >> 32) + (unsigned)(incl >> 32) - c1);
        g_off[0][i] = off0; g_cur[0][i] = off0; g_cnt[0][i] = 0;
        g_off[1][i] = off1; g_cur[1][i] = off1; g_cnt[1][i] = 0;
        if (i == n - 1) {
            g_off[0][n] = off0 + (int)c0;
            g_off[1][n] = off1 + (int)c1;
        }
    }
    if (tid == 0) {
        __threadfence();
        int d = atomicAdd(&g_done, 1);
        if (d == nb - 1) {               // last block: reset lookback state
            for (int j = 0; j < nb; j++) { g_look[0][j] = 0u; g_look[1][j] = 0u; }
            g_done = 0;
        }
    }

    // ---- tail: packed angular-edge table (chip is underutilized here)
    int stride = gridDim.x * blockDim.x;
    for (int j = b * 1024 + tid; j < n_edges_ang; j += stride) {
        int s = species[edge_dst_ang[j]];
        g_eang[j] = make_float4(dang[j], swang[j],
                                vtab[s * VDIM + 0], vtab[s * VDIM + 1]);
    }
}

// ---------------------------------------------------------------------------
// K3: build records for both CSRs (atom-sorted slots).
// ---------------------------------------------------------------------------
__global__ void scatter_kernel(const float* __restrict__ angles,
                               const int*  __restrict__ central,
                               const int*  __restrict__ asrc,
                               const int*  __restrict__ adst,
                               const float* __restrict__ dist,
                               const float* __restrict__ sw,
                               const int*  __restrict__ esrc,
                               const int*  __restrict__ edst,
                               const int*  __restrict__ species,
                               int n_angles, int n_edges) {
    int t = blockIdx.x * blockDim.x + threadIdx.x;
    if (t < n_angles) {
        int es = asrc[t], ed = adst[t];
        float4 ps = g_eang[es];
        float4 pd = g_eang[ed];
        float d12  = 0.5f * (ps.x + pd.x);
        float sw12 = ps.y * pd.y;
        float ca   = __cosf(angles[t]);
        float vp0 = ps.z + pd.z, vp1 = ps.w + pd.w;
        float vm0 = ps.z * pd.z, vm1 = ps.w * pd.w;
        __half2 h01 = __floats2half2_rn(sw12 * vp0 * vm0, sw12 * vp0 * vm1);
        __half2 h23 = __floats2half2_rn(sw12 * vp1 * vm0, sw12 * vp1 * vm1);
        int pos = atomicAdd(&g_cur[0][central[t]], 1);
        float4 r;
        r.x = d12;
        r.y = ca;
        r.z = __uint_as_float(*reinterpret_cast<unsigned*>(&h01));
        r.w = __uint_as_float(*reinterpret_cast<unsigned*>(&h23));
        g_arec[pos] = r;
    }
    if (t < n_edges) {
        float d = dist[t], s = sw[t];
        int sd = species[edst[t]];
        int pos = atomicAdd(&g_cur[1][esrc[t]], 1);
        // species in low 4 mantissa bits of sw (<=15 ulp perturbation, ~2e-6 rel)
        unsigned sb = (__float_as_uint(s) & ~15u) | (unsigned)sd;
        g_rrec[pos] = make_float2(d, __uint_as_float(sb));
    }
}

// ---------------------------------------------------------------------------
// K4: fused accumulation (exact R11 structure — proven 76.8us @ 32 regs).
// One warp per atom; no atomics. Scalar math, moment accumulators.
// Also writes the one-hot block (row is resident here anyway).
// ---------------------------------------------------------------------------
__global__ void accum_kernel(float* __restrict__ out,
                             const int* __restrict__ species, int n_atoms) {
    __shared__ float sacc[8][2][16 * 17];
    int w    = threadIdx.x >> 5;
    int lane = threadIdx.x & 31;
    int atom = blockIdx.x * 8 + w;
    if (atom >= n_atoms) return;

    // ---- one-hot
    if (lane < NSPEC) {
        int sp = species[atom];
        out[(long)atom * ROW + lane] = (lane == sp) ? 1.0f : 0.0f;
    }

    // ---- radial
    float* mybuf = &sacc[w][0][0];
    for (int k = lane; k < 2 * 16 * 17; k += 32) mybuf[k] = 0.f;
    __syncwarp();

    int hw = lane >> 4, lr = lane & 15;
    float ctr = STEP_R * (float)lr;
    float BR1 = -2.0f * KR * ctr;
    float BR2 = KR * ctr * ctr;
    float* hbuf = &sacc[w][hw][0] + lr * 17;
    {
        int s0 = g_off[1][atom], e0 = g_off[1][atom + 1];
        for (int i = s0 + hw; i < e0; i += 2) {
            float2 r = g_rrec[i];
            int sd = (int)(__float_as_uint(r.y) & 15u);
            float q = fmaf(KR, r.x, BR1);
            float v = r.y * ex2f(fmaf(q, r.x, BR2));
            hbuf[sd] += v;
        }
    }
    __syncwarp();
    {
        float* obase = out + (long)atom * ROW + RAD_OFF;
        #pragma unroll
        for (int k = 0; k < 8; k++) {
            int idx = k * 32 + lane;          // coalesced
            int r = idx >> 4, s = idx & 15;
            obase[idx] = sacc[w][0][r * 17 + s] + sacc[w][1][r * 17 + s];
        }
    }

    // ---- angular: lane owns (ra = lane>>2, v = lane&3); moment accumulators
    int ra = lane >> 2, v = lane & 3;
    float center = 0.5f * (float)ra;
    float B1 = -2.0f * KA * center;       // q = fma(KA, x, B1)
    float B2 = KA * center * center;      // e = fma(q, x, B2)
    bool selw = (v & 2) != 0;             // loop-invariant half selector
    int  sh   = (v & 1) << 4;             // loop-invariant shift
    float m0 = 0.f, m1 = 0.f, m2 = 0.f, m3 = 0.f, m4 = 0.f;
    int s1 = g_off[0][atom], e1 = g_off[0][atom + 1];
    const float4* __restrict__ rec = g_arec;

    int i = s1;
    for (; i + 4 <= e1; i += 4) {
        float4 p  = rec[i];
        float4 q4 = rec[i + 1];
        float4 r  = rec[i + 2];
        float4 s  = rec[i + 3];
        #pragma unroll
        for (int k = 0; k < 4; k++) {
            float4 c = (k == 0) ? p : (k == 1) ? q4 : (k == 2) ? r : s;
            unsigned u32 = selw ? __float_as_uint(c.w) : __float_as_uint(c.z);
            float val = __half2float(__ushort_as_half((unsigned short)(u32 >> sh)));
            float qq = fmaf(KA, c.x, B1);
            float tt = ex2f(fmaf(qq, c.x, B2)) * val;
            float ca = c.y;
            float ca2 = ca * ca;
            float u1  = ca * tt;
            float u2  = ca2 * tt;
            m0 += tt;
            m1 += u1;
            m2 += u2;
            m3 = fmaf(ca2, u1, m3);
            m4 = fmaf(ca2, u2, m4);
        }
    }
    for (; i < e1; i++) {
        float4 c = rec[i];
        unsigned u32 = selw ? __float_as_uint(c.w) : __float_as_uint(c.z);
        float val = __half2float(__ushort_as_half((unsigned short)(u32 >> sh)));
        float qq = fmaf(KA, c.x, B1);
        float tt = ex2f(fmaf(qq, c.x, B2)) * val;
        float ca = c.y;
        float ca2 = ca * ca;
        float u1  = ca * tt;
        float u2  = ca2 * tt;
        m0 += tt;
        m1 += u1;
        m2 += u2;
        m3 = fmaf(ca2, u1, m3);
        m4 = fmaf(ca2, u2, m4);
    }

    // cos(k*theta) recovery: a2=2m2-m0, a3=4m3-3m1, a4=8m4-8m2+m0
    float* base = out + (long)atom * ROW + ANG_OFF + ra * 20 + v;
    base[0]  = m0;
    base[4]  = m1;
    base[8]  = 2.0f * m2 - m0;
    base[12] = 4.0f * m3 - 3.0f * m1;
    base[16] = 8.0f * (m4 - m2) + m0;
}

// ---------------------------------------------------------------------------
// Launch
// ---------------------------------------------------------------------------
extern "C" void kernel_launch(void* const* d_in, const int* in_sizes, int n_in,
                              void* d_out, int out_size) {
    const int*   species      = (const int*)  d_in[0];
    const float* distances    = (const float*)d_in[1];
    const float* switch_      = (const float*)d_in[2];
    const int*   edge_src     = (const int*)  d_in[3];
    const int*   edge_dst     = (const int*)  d_in[4];
    const float* angles       = (const float*)d_in[5];
    const float* dang         = (const float*)d_in[6];
    const float* switch_ang   = (const float*)d_in[7];
    const int*   central_atom = (const int*)  d_in[8];
    const int*   angle_src    = (const int*)  d_in[9];
    const int*   angle_dst    = (const int*)  d_in[10];
    const int*   edge_dst_ang = (const int*)  d_in[11];
    const float* valence_tab  = (const float*)d_in[12];

    float* out = (float*)d_out;

    int n_atoms     = in_sizes[0];
    int n_edges     = in_sizes[1];
    int n_angles    = in_sizes[5];
    int n_edges_ang = in_sizes[6];

    // K1: histograms (counters zero on entry by invariant)
    int n1 = n_angles > n_edges ? n_angles : n_edges;
    prep_hist_kernel<<<(n1 + 255) / 256, 256>>>(central_atom, edge_src,
                                                n_angles, n_edges);

    // K2: single-pass decoupled-lookback scan + eang table build
    int nb = (n_atoms + 1023) / 1024;
    scan_kernel<<<nb, 1024>>>(species, edge_dst_ang, valence_tab,
                              dang, switch_ang, n_edges_ang, n_atoms, nb);

    // K3: scatter records
    scatter_kernel<<<(n1 + 255) / 256, 256>>>(angles, central_atom,
                                              angle_src, angle_dst,
                                              distances, switch_, edge_src,
                                              edge_dst, species,
                                              n_angles, n_edges);

    // K4: fused accumulation (one warp per atom) + one-hot
    accum_kernel<<<(n_atoms + 7) / 8, 256>>>(out, species, n_atoms);
}